// round 1
// baseline (speedup 1.0000x reference)
#include <cuda_runtime.h>
#include <math.h>

// Problem constants (fixed by the dataset)
#define NP 200000
#define NA 200000
#define NE 2000000
#define H  64
#define DP 128
#define DA 64
#define OUTD 32

// ---------------------------------------------------------------------------
// Device scratch (no cudaMalloc allowed) — ~310 MB of static global arrays.
// ---------------------------------------------------------------------------
__device__ float g_featP[(size_t)NP * H];
__device__ float g_featA[(size_t)NA * H];
__device__ float g_xP[(size_t)NP * H];
__device__ float g_xA[(size_t)NA * H];
__device__ float g_aggP[(size_t)NP * H];
__device__ float g_aggA[(size_t)NA * H];
__device__ float g_x1P[NP];
__device__ float g_h1P[NP];
__device__ float g_divP[NP];
__device__ float g_x1A[NA];
__device__ float g_h1A[NA];
__device__ float g_divA[NA];

// ---------------------------------------------------------------------------
// Helpers
// ---------------------------------------------------------------------------
__device__ __forceinline__ void red_add_v4(float* addr, float4 v) {
    asm volatile("red.global.add.v4.f32 [%0], {%1,%2,%3,%4};"
                 :: "l"(addr), "f"(v.x), "f"(v.y), "f"(v.z), "f"(v.w)
                 : "memory");
}
__device__ __forceinline__ void red_add_f32(float* addr, float v) {
    asm volatile("red.global.add.f32 [%0], %1;"
                 :: "l"(addr), "f"(v) : "memory");
}
__device__ __forceinline__ float leaky02(float v) {
    return v > 0.0f ? v : 0.2f * v;
}

// ---------------------------------------------------------------------------
// GEMM: Y[N, NOUT] = act(X[N, K] @ W[K, NOUT] + b)
// Block = 256 threads; each thread computes a 4-row x 4-col tile.
// W staged in shared memory.
// ---------------------------------------------------------------------------
template<int K, int NOUT, bool RELU>
__global__ void __launch_bounds__(256)
gemm_kernel(const float* __restrict__ X, const float* __restrict__ W,
            const float* __restrict__ bias, float* __restrict__ Y, int N)
{
    constexpr int TPR = NOUT / 4;     // threads spanning the NOUT dim
    constexpr int RG  = 256 / TPR;    // row-groups per block
    constexpr int RPB = RG * 4;       // rows per block

    __shared__ float sW[K * NOUT];
    for (int i = threadIdx.x; i < K * NOUT; i += 256) sW[i] = W[i];
    __syncthreads();

    const int tg = threadIdx.x / TPR;
    const int cg = threadIdx.x % TPR;
    const int r0 = blockIdx.x * RPB + tg * 4;
    const int c0 = cg * 4;

    float4 b4 = *(const float4*)(bias + c0);
    float4 acc[4];
    #pragma unroll
    for (int r = 0; r < 4; r++) acc[r] = b4;

    // Clamp row reads so the tail block stays in-bounds; writes are guarded.
    int rr[4];
    #pragma unroll
    for (int r = 0; r < 4; r++) {
        int q = r0 + r;
        rr[r] = q < N ? q : (N - 1);
    }

    #pragma unroll 4
    for (int k4 = 0; k4 < K / 4; k4++) {
        const int kb = k4 * 4;
        float4 w0 = *(const float4*)(&sW[(kb + 0) * NOUT + c0]);
        float4 w1 = *(const float4*)(&sW[(kb + 1) * NOUT + c0]);
        float4 w2 = *(const float4*)(&sW[(kb + 2) * NOUT + c0]);
        float4 w3 = *(const float4*)(&sW[(kb + 3) * NOUT + c0]);
        #pragma unroll
        for (int r = 0; r < 4; r++) {
            float4 xv = *(const float4*)(X + (size_t)rr[r] * K + kb);
            acc[r].x += xv.x * w0.x + xv.y * w1.x + xv.z * w2.x + xv.w * w3.x;
            acc[r].y += xv.x * w0.y + xv.y * w1.y + xv.z * w2.y + xv.w * w3.y;
            acc[r].z += xv.x * w0.z + xv.y * w1.z + xv.z * w2.z + xv.w * w3.z;
            acc[r].w += xv.x * w0.w + xv.y * w1.w + xv.z * w2.w + xv.w * w3.w;
        }
    }

    #pragma unroll
    for (int r = 0; r < 4; r++) {
        int q = r0 + r;
        if (q < N) {
            float4 v = acc[r];
            if (RELU) {
                v.x = fmaxf(v.x, 0.0f); v.y = fmaxf(v.y, 0.0f);
                v.z = fmaxf(v.z, 0.0f); v.w = fmaxf(v.w, 0.0f);
            }
            *(float4*)(Y + (size_t)q * NOUT + c0) = v;
        }
    }
}

// ---------------------------------------------------------------------------
// Node prep: one warp per node.
//   x1   = x . a1own          (this set as SRC of its edge type)
//   xa2  = x . a2own
//   h1   = x . a2oth          (this set as DST of the other edge type)
//   w2   = exp(leaky(x1 + xa2))
//   div  = w2 ; agg = w2 * x  (accumulator init — edge kernel RED-adds on top)
// ---------------------------------------------------------------------------
__global__ void __launch_bounds__(256)
nodeprep_kernel(const float* __restrict__ X, int N,
                const float* __restrict__ a1, const float* __restrict__ a2own,
                const float* __restrict__ a2oth,
                float* __restrict__ x1o, float* __restrict__ h1o,
                float* __restrict__ divo, float* __restrict__ agg)
{
    int warp = (blockIdx.x * blockDim.x + threadIdx.x) >> 5;
    int lane = threadIdx.x & 31;
    if (warp >= N) return;

    float2 xv = *(const float2*)(X + (size_t)warp * H + lane * 2);
    float2 v1 = *(const float2*)(a1 + lane * 2);
    float2 v2 = *(const float2*)(a2own + lane * 2);
    float2 v3 = *(const float2*)(a2oth + lane * 2);

    float d1 = xv.x * v1.x + xv.y * v1.y;
    float d2 = xv.x * v2.x + xv.y * v2.y;
    float d3 = xv.x * v3.x + xv.y * v3.y;
    #pragma unroll
    for (int o = 16; o; o >>= 1) {
        d1 += __shfl_xor_sync(0xFFFFFFFFu, d1, o);
        d2 += __shfl_xor_sync(0xFFFFFFFFu, d2, o);
        d3 += __shfl_xor_sync(0xFFFFFFFFu, d3, o);
    }

    float w2 = __expf(leaky02(d1 + d2));
    if (lane == 0) {
        x1o[warp]  = d1;
        h1o[warp]  = d3;
        divo[warp] = w2;
    }
    float2 ag;
    ag.x = w2 * xv.x;
    ag.y = w2 * xv.y;
    *(float2*)(agg + (size_t)warp * H + lane * 2) = ag;
}

// ---------------------------------------------------------------------------
// Edge kernel: 16 lanes per edge.
//   w1 = exp(leaky(x1[s] + h1[t]))
//   div[s] += w1 ; agg[s][:] += w1 * hfeat[t][:]
// ---------------------------------------------------------------------------
__global__ void __launch_bounds__(256)
edge_kernel(const int* __restrict__ src, const int* __restrict__ tgt, int E,
            const float* __restrict__ x1, const float* __restrict__ h1,
            const float* __restrict__ hfeat,
            float* __restrict__ divp, float* __restrict__ agg)
{
    long long gid = (long long)blockIdx.x * blockDim.x + threadIdx.x;
    int e  = (int)(gid >> 4);
    int li = (int)(gid & 15);
    if (e >= E) return;

    int s = src[e];
    int t = tgt[e];
    float w1 = __expf(leaky02(x1[s] + h1[t]));

    float4 hv = *(const float4*)(hfeat + (size_t)t * H + li * 4);
    float4 v;
    v.x = w1 * hv.x; v.y = w1 * hv.y; v.z = w1 * hv.z; v.w = w1 * hv.w;
    red_add_v4(agg + (size_t)s * H + li * 4, v);
    if (li == 0) red_add_f32(divp + s, w1);
}

// ---------------------------------------------------------------------------
// Finalize: feat = elu(agg / div), float2 per thread.
// ---------------------------------------------------------------------------
__global__ void __launch_bounds__(256)
finalize_kernel(const float* __restrict__ agg, const float* __restrict__ divp,
                float* __restrict__ out, int N)
{
    int gid = blockIdx.x * blockDim.x + threadIdx.x;   // over N*32 float2's
    if (gid >= N * 32) return;
    int n = gid >> 5;
    int j = (gid & 31) * 2;
    float d = divp[n];
    float inv = 1.0f / d;
    float2 a = *(const float2*)(agg + (size_t)n * H + j);
    float vx = a.x * inv;
    float vy = a.y * inv;
    vx = vx > 0.0f ? vx : (__expf(vx) - 1.0f);
    vy = vy > 0.0f ? vy : (__expf(vy) - 1.0f);
    float2 o; o.x = vx; o.y = vy;
    *(float2*)(out + (size_t)n * H + j) = o;
}

// ---------------------------------------------------------------------------
// Launch
// ---------------------------------------------------------------------------
extern "C" void kernel_launch(void* const* d_in, const int* in_sizes, int n_in,
                              void* d_out, int out_size)
{
    const float* x_P     = (const float*)d_in[0];
    const float* x_A     = (const float*)d_in[1];
    const int*   ei_pa   = (const int*)d_in[2];   // [2, E]: row0 = P idx (src), row1 = A idx (dst)
    const int*   ei_ap   = (const int*)d_in[3];   // [2, E]: row0 = A idx (src), row1 = P idx (dst)
    const float* fc1_P_w = (const float*)d_in[4];
    const float* fc1_P_b = (const float*)d_in[5];
    const float* fc1_A_w = (const float*)d_in[6];
    const float* fc1_A_b = (const float*)d_in[7];
    const float* fcs_w   = (const float*)d_in[8];   // [2, 64, 64]
    const float* fcs_b   = (const float*)d_in[9];   // [2, 64]
    const float* a1_pa   = (const float*)d_in[10];  // [2, 64]
    const float* a2_pa   = (const float*)d_in[11];
    const float* a1_ap   = (const float*)d_in[12];
    const float* a2_ap   = (const float*)d_in[13];
    const float* fc2_w   = (const float*)d_in[14];
    const float* fc2_b   = (const float*)d_in[15];
    float* out = (float*)d_out;

    float *featP, *featA, *xP, *xA, *aggP, *aggA;
    float *x1P, *h1P, *divP, *x1A, *h1A, *divA;
    cudaGetSymbolAddress((void**)&featP, g_featP);
    cudaGetSymbolAddress((void**)&featA, g_featA);
    cudaGetSymbolAddress((void**)&xP,    g_xP);
    cudaGetSymbolAddress((void**)&xA,    g_xA);
    cudaGetSymbolAddress((void**)&aggP,  g_aggP);
    cudaGetSymbolAddress((void**)&aggA,  g_aggA);
    cudaGetSymbolAddress((void**)&x1P,   g_x1P);
    cudaGetSymbolAddress((void**)&h1P,   g_h1P);
    cudaGetSymbolAddress((void**)&divP,  g_divP);
    cudaGetSymbolAddress((void**)&x1A,   g_x1A);
    cudaGetSymbolAddress((void**)&h1A,   g_h1A);
    cudaGetSymbolAddress((void**)&divA,  g_divA);

    const int gemm64_blocks  = (NP + 63) / 64;          // RPB = 64 for NOUT=64
    const int gemm32_blocks  = (NP + 127) / 128;        // RPB = 128 for NOUT=32
    const int node_blocks    = (NP + 7) / 8;            // 8 warps (nodes) per block
    const int edge_blocks    = (int)(((long long)NE * 16 + 255) / 256);
    const int fin_blocks     = (NP * 32 + 255) / 256;

    // Input projection + ReLU
    gemm_kernel<DP, H, true><<<gemm64_blocks, 256>>>(x_P, fc1_P_w, fc1_P_b, featP, NP);
    gemm_kernel<DA, H, true><<<gemm64_blocks, 256>>>(x_A, fc1_A_w, fc1_A_b, featA, NA);

    for (int hop = 0; hop < 2; hop++) {
        const float* W  = fcs_w + (size_t)hop * H * H;
        const float* b  = fcs_b + (size_t)hop * H;
        const float* v1pa = a1_pa + (size_t)hop * H;
        const float* v2pa = a2_pa + (size_t)hop * H;
        const float* v1ap = a1_ap + (size_t)hop * H;
        const float* v2ap = a2_ap + (size_t)hop * H;

        // Shared fcs GEMM (no activation)
        gemm_kernel<H, H, false><<<gemm64_blocks, 256>>>(featP, W, b, xP, NP);
        gemm_kernel<H, H, false><<<gemm64_blocks, 256>>>(featA, W, b, xA, NA);

        // Node prep:
        //  P is src of pa edges (a1_pa/a2_pa) and dst of ap edges (a2_ap)
        //  A is src of ap edges (a1_ap/a2_ap) and dst of pa edges (a2_pa)
        nodeprep_kernel<<<node_blocks, 256>>>(xP, NP, v1pa, v2pa, v2ap, x1P, h1P, divP, aggP);
        nodeprep_kernel<<<node_blocks, 256>>>(xA, NA, v1ap, v2ap, v2pa, x1A, h1A, divA, aggA);

        // Edge aggregation (atomic RED into src-side accumulators)
        edge_kernel<<<edge_blocks, 256>>>(ei_pa, ei_pa + NE, NE, x1P, h1A, xA, divP, aggP);
        edge_kernel<<<edge_blocks, 256>>>(ei_ap, ei_ap + NE, NE, x1A, h1P, xP, divA, aggA);

        // feat = elu(agg / div)
        finalize_kernel<<<fin_blocks, 256>>>(aggP, divP, featP, NP);
        finalize_kernel<<<fin_blocks, 256>>>(aggA, divA, featA, NA);
    }

    // Output head: [200000, 32]
    gemm_kernel<H, OUTD, false><<<gemm32_blocks, 256>>>(featP, fc2_w, fc2_b, out, NP);
}